// round 4
// baseline (speedup 1.0000x reference)
#include <cuda_runtime.h>
#include <cstdint>

#define NN 50000
#define EE 800000
#define NG 512
#define N4 (NN / 4)          // 12500 (NN divisible by 4)
#define NBLK 49              // ceil(N4 / 256)

// ---------------- static device scratch ----------------
__device__ float g_buf1[NN * 256];       // GEMM outs [N,256] (td|bu halves)
__device__ float g_bufTd[NN * 128];
__device__ float g_bufBu[NN * 128];
__device__ float g_pool[NG * 256];       // pooled concat: bu @0, td @128
__device__ float g_mlp[NG * 256];
__device__ int   g_deg[2 * NN];          // [0,NN)=indeg(dst) td; [NN,2NN)=outdeg(src) bu
__device__ float g_dinv[2 * NN];
__device__ int   g_off_td[NN + 1];
__device__ int   g_off_bu[NN + 1];
__device__ int   g_cur_td[NN];
__device__ int   g_cur_bu[NN];
__device__ int   g_part[2 * NBLK];
__device__ int   g_csr_td[EE];
__device__ int   g_csr_bu[EE];

// ---------------- utility kernels ----------------
__global__ void zero_f4(float* p, int n4) {
    int i = blockIdx.x * blockDim.x + threadIdx.x;
    if (i < n4) ((float4*)p)[i] = make_float4(0.f, 0.f, 0.f, 0.f);
}
__global__ void zero_i(int* p, int n) {
    int i = blockIdx.x * blockDim.x + threadIdx.x;
    if (i < n) p[i] = 0;
}
__global__ void deg_kernel(const int* __restrict__ src, const int* __restrict__ dst,
                           int* deg_in, int* deg_out, int e) {
    int i = blockIdx.x * blockDim.x + threadIdx.x;
    if (i < e) {
        atomicAdd(&deg_in[dst[i]], 1);
        atomicAdd(&deg_out[src[i]], 1);
    }
}
__global__ void dinv_kernel(const int* __restrict__ deg, float* __restrict__ dinv, int n) {
    int i = blockIdx.x * blockDim.x + threadIdx.x;
    if (i < n) dinv[i] = rsqrtf((float)deg[i] + 1.0f);
}

// ---------------- 3-phase parallel scan ----------------
// Phase 1: per-block sums (block = 1024 elems via int4). grid (NBLK, 2).
__global__ void scan_bsum(const int* __restrict__ deg, int* __restrict__ part) {
    int dir = blockIdx.y, b = blockIdx.x, tid = threadIdx.x;
    const int4* d4 = (const int4*)(deg + dir * NN);
    int i4 = b * 256 + tid;
    int s = 0;
    if (i4 < N4) { int4 v = d4[i4]; s = v.x + v.y + v.z + v.w; }
#pragma unroll
    for (int d = 16; d > 0; d >>= 1) s += __shfl_down_sync(0xffffffffu, s, d);
    __shared__ int wt[8];
    if ((tid & 31) == 0) wt[tid >> 5] = s;
    __syncthreads();
    if (tid < 8) {
        int v = wt[tid];
#pragma unroll
        for (int d = 4; d > 0; d >>= 1) v += __shfl_down_sync(0xffu, v, d);
        if (tid == 0) part[dir * NBLK + b] = v;
    }
}

// Phase 2: scan the partials (1 warp per direction); write totals to off[NN].
__global__ void scan_part(int* __restrict__ part, int* __restrict__ off_td,
                          int* __restrict__ off_bu) {
    int w = threadIdx.x >> 5, lane = threadIdx.x & 31;
    if (w >= 2) return;
    int* p = part + w * NBLK;
    int v0 = (lane < NBLK) ? p[lane] : 0;
    int v1 = (lane + 32 < NBLK) ? p[lane + 32] : 0;
    int s0 = v0;
#pragma unroll
    for (int d = 1; d < 32; d <<= 1) {
        int t = __shfl_up_sync(0xffffffffu, s0, d);
        if (lane >= d) s0 += t;
    }
    int tot0 = __shfl_sync(0xffffffffu, s0, 31);
    int s1 = v1;
#pragma unroll
    for (int d = 1; d < 32; d <<= 1) {
        int t = __shfl_up_sync(0xffffffffu, s1, d);
        if (lane >= d) s1 += t;
    }
    s1 += tot0;
    if (lane < NBLK) p[lane] = s0 - v0;
    if (lane + 32 < NBLK) p[lane + 32] = s1 - v1;
    int total = __shfl_sync(0xffffffffu, s1, 31);
    if (lane == 0) (w == 0 ? off_td : off_bu)[NN] = total;
}

// Phase 3: block-local scan + partial offset; writes off[] and cur[]. grid (NBLK, 2).
__global__ void scan_write(const int* __restrict__ deg, const int* __restrict__ part,
                           int* __restrict__ off_td, int* __restrict__ off_bu,
                           int* __restrict__ cur_td, int* __restrict__ cur_bu) {
    int dir = blockIdx.y, b = blockIdx.x, tid = threadIdx.x;
    int lane = tid & 31, w = tid >> 5;
    const int4* d4 = (const int4*)(deg + dir * NN);
    int i4 = b * 256 + tid;
    int4 v = make_int4(0, 0, 0, 0);
    if (i4 < N4) v = d4[i4];
    int ts = v.x + v.y + v.z + v.w;
    int incl = ts;
#pragma unroll
    for (int d = 1; d < 32; d <<= 1) {
        int t = __shfl_up_sync(0xffffffffu, incl, d);
        if (lane >= d) incl += t;
    }
    __shared__ int wt[8];
    if (lane == 31) wt[w] = incl;
    __syncthreads();
    if (w == 0 && lane < 8) {
        int x = wt[lane];
        int sx = x;
#pragma unroll
        for (int d = 1; d < 8; d <<= 1) {
            int t = __shfl_up_sync(0xffu, sx, d);
            if (lane >= d) sx += t;
        }
        wt[lane] = sx - x;
    }
    __syncthreads();
    int base = part[dir * NBLK + b] + wt[w] + (incl - ts);
    int* off = dir ? off_bu : off_td;
    int* cur = dir ? cur_bu : cur_td;
    if (i4 < N4) {
        int4 o;
        o.x = base;
        o.y = base + v.x;
        o.z = o.y + v.y;
        o.w = o.z + v.z;
        ((int4*)off)[i4] = o;
        ((int4*)cur)[i4] = o;
    }
}

__global__ void scatter_kernel(const int* __restrict__ src, const int* __restrict__ dst,
                               int* cur_td, int* cur_bu,
                               int* __restrict__ csr_td, int* __restrict__ csr_bu, int e) {
    int i = blockIdx.x * blockDim.x + threadIdx.x;
    if (i < e) {
        int s = src[i], d = dst[i];
        csr_td[atomicAdd(&cur_td[d], 1)] = s;
        csr_bu[atomicAdd(&cur_bu[s], 1)] = d;
    }
}

// ---------------- TF32 tensor-core GEMM (cp.async double-buffered) ----------------
__device__ __forceinline__ uint32_t f2tf(float x) {
    uint32_t r;
    asm("cvt.rna.tf32.f32 %0, %1;" : "=r"(r) : "f"(x));
    return r;
}

// C[M, n-window] = A[M,K] @ B[K,ldb] (+rowscale, +bias, +relu). Tile 128x128, BK=16.
__global__ __launch_bounds__(256, 2)
void gemm_tf32(const float* __restrict__ A, const float* __restrict__ B,
               const float* __restrict__ bias, const float* __restrict__ rowscale,
               float* __restrict__ C, int M, int K, int ldb, int ldc, int relu) {
    __shared__ __align__(16) float As[2][128][20];   // [m][k] pad->20: conflict-free
    __shared__ __align__(16) float Bs[2][16][136];   // [k][n] pad->136: conflict-free

    const int tid = threadIdx.x;
    const int lane = tid & 31;
    const int warp = tid >> 5;
    const int g = lane >> 2, tig = lane & 3;
    const int m0 = blockIdx.x * 128, n0 = blockIdx.y * 128;
    const int wm = (warp & 1) * 64, wn = (warp >> 1) * 32;

    const uint32_t sA = (uint32_t)__cvta_generic_to_shared(&As[0][0][0]);
    const uint32_t sB = (uint32_t)__cvta_generic_to_shared(&Bs[0][0][0]);

    float acc[4][4][4];
#pragma unroll
    for (int i = 0; i < 4; i++)
#pragma unroll
        for (int j = 0; j < 4; j++)
#pragma unroll
            for (int c = 0; c < 4; c++) acc[i][j][c] = 0.f;

    const int T = K >> 4;

#define ISSUE_TILE(t)                                                              \
    {                                                                              \
        int k0 = (t) * 16, buf = (t) & 1;                                          \
        _Pragma("unroll")                                                          \
        for (int l = 0; l < 2; l++) {                                              \
            int idx = tid + l * 256;                                               \
            int row = idx >> 2, kq = idx & 3;                                      \
            int gm = m0 + row;                                                     \
            const float* srcp = A + (size_t)(gm < M ? gm : 0) * K + k0 + kq * 4;   \
            uint32_t dstp = sA + (uint32_t)((buf * 2560 + row * 20 + kq * 4) * 4); \
            int sz = gm < M ? 16 : 0;                                              \
            asm volatile("cp.async.cg.shared.global [%0], [%1], 16, %2;"           \
                         :: "r"(dstp), "l"(srcp), "r"(sz));                        \
        }                                                                          \
        _Pragma("unroll")                                                          \
        for (int l = 0; l < 2; l++) {                                              \
            int idx = tid + l * 256;                                               \
            int row = idx >> 5, c4 = idx & 31;                                     \
            const float* srcp = B + (size_t)(k0 + row) * ldb + n0 + c4 * 4;        \
            uint32_t dstp = sB + (uint32_t)((buf * 2176 + row * 136 + c4 * 4) * 4);\
            asm volatile("cp.async.cg.shared.global [%0], [%1], 16;"               \
                         :: "r"(dstp), "l"(srcp));                                 \
        }                                                                          \
        asm volatile("cp.async.commit_group;");                                    \
    }

    ISSUE_TILE(0);
    for (int t = 0; t < T; t++) {
        if (t + 1 < T) {
            ISSUE_TILE(t + 1);
            asm volatile("cp.async.wait_group 1;");
        } else {
            asm volatile("cp.async.wait_group 0;");
        }
        __syncthreads();
        const int buf = t & 1;
#pragma unroll
        for (int kk = 0; kk < 16; kk += 8) {
            uint32_t af[4][4], bf[4][2];
#pragma unroll
            for (int i = 0; i < 4; i++) {
                int mb = wm + i * 16 + g;
                af[i][0] = f2tf(As[buf][mb][kk + tig]);
                af[i][1] = f2tf(As[buf][mb + 8][kk + tig]);
                af[i][2] = f2tf(As[buf][mb][kk + tig + 4]);
                af[i][3] = f2tf(As[buf][mb + 8][kk + tig + 4]);
            }
#pragma unroll
            for (int j = 0; j < 4; j++) {
                int nb = wn + j * 8 + g;
                bf[j][0] = f2tf(Bs[buf][kk + tig][nb]);
                bf[j][1] = f2tf(Bs[buf][kk + tig + 4][nb]);
            }
#pragma unroll
            for (int i = 0; i < 4; i++)
#pragma unroll
                for (int j = 0; j < 4; j++) {
                    asm volatile(
                        "mma.sync.aligned.m16n8k8.row.col.f32.tf32.tf32.f32 "
                        "{%0,%1,%2,%3}, {%4,%5,%6,%7}, {%8,%9}, {%0,%1,%2,%3};"
                        : "+f"(acc[i][j][0]), "+f"(acc[i][j][1]),
                          "+f"(acc[i][j][2]), "+f"(acc[i][j][3])
                        : "r"(af[i][0]), "r"(af[i][1]), "r"(af[i][2]), "r"(af[i][3]),
                          "r"(bf[j][0]), "r"(bf[j][1]));
                }
        }
        __syncthreads();
    }
#undef ISSUE_TILE

#pragma unroll
    for (int i = 0; i < 4; i++) {
        int r0 = m0 + wm + i * 16 + g;
        int r1 = r0 + 8;
        float s0 = 1.f, s1 = 1.f;
        if (rowscale) {
            if (r0 < M) s0 = rowscale[r0];
            if (r1 < M) s1 = rowscale[r1];
        }
#pragma unroll
        for (int j = 0; j < 4; j++) {
            int cb = n0 + wn + j * 8 + 2 * tig;
            float b0 = 0.f, b1 = 0.f;
            if (bias) { b0 = bias[cb]; b1 = bias[cb + 1]; }
            float v0 = acc[i][j][0] * s0 + b0, v1 = acc[i][j][1] * s0 + b1;
            float v2 = acc[i][j][2] * s1 + b0, v3 = acc[i][j][3] * s1 + b1;
            if (relu) {
                v0 = fmaxf(v0, 0.f); v1 = fmaxf(v1, 0.f);
                v2 = fmaxf(v2, 0.f); v3 = fmaxf(v3, 0.f);
            }
            if (r0 < M) *(float2*)(C + (size_t)r0 * ldc + cb) = make_float2(v0, v1);
            if (r1 < M) *(float2*)(C + (size_t)r1 * ldc + cb) = make_float2(v2, v3);
        }
    }
}

// ---------------- CSR aggregation on prescaled h' = dinv*h ----------------
// out[d] = act( dinv[d]*(Σ_s h'[s] + h'[d]) + b )
__global__ void agg_csr(const float* __restrict__ h, int hs, int ho,
                        const int* __restrict__ csr, const int* __restrict__ off,
                        const float* __restrict__ dinv, const float* __restrict__ bias,
                        float* __restrict__ out, int os, int oo, int relu,
                        const int* __restrict__ batch, float* __restrict__ pool, int po) {
    int node = (blockIdx.x * blockDim.x + threadIdx.x) >> 5;
    if (node >= NN) return;
    int lane = threadIdx.x & 31;

    int e0 = off[node], e1 = off[node + 1];
    float4 acc = make_float4(0.f, 0.f, 0.f, 0.f);
    for (int base = e0; base < e1; base += 32) {
        int j = base + lane;
        int s = (j < e1) ? csr[j] : 0;
        int cnt = min(32, e1 - base);
        for (int t = 0; t < cnt; t++) {
            int ss = __shfl_sync(0xffffffffu, s, t);
            float4 v = *(const float4*)(h + (size_t)ss * hs + ho + lane * 4);
            acc.x += v.x; acc.y += v.y; acc.z += v.z; acc.w += v.w;
        }
    }
    float di = dinv[node];
    float4 sv = *(const float4*)(h + (size_t)node * hs + ho + lane * 4);
    float4 bv = *(const float4*)(bias + lane * 4);
    float4 r;
    r.x = fmaf(di, acc.x + sv.x, bv.x);
    r.y = fmaf(di, acc.y + sv.y, bv.y);
    r.z = fmaf(di, acc.z + sv.z, bv.z);
    r.w = fmaf(di, acc.w + sv.w, bv.w);
    if (relu) {
        r.x = fmaxf(r.x, 0.f); r.y = fmaxf(r.y, 0.f);
        r.z = fmaxf(r.z, 0.f); r.w = fmaxf(r.w, 0.f);
    }
    if (pool) {
        int gi = batch[node];
        float* p = pool + (size_t)gi * 256 + po + lane * 4;
        atomicAdd(p + 0, r.x);
        atomicAdd(p + 1, r.y);
        atomicAdd(p + 2, r.z);
        atomicAdd(p + 3, r.w);
    } else {
        *(float4*)(out + (size_t)node * os + oo + lane * 4) = r;
    }
}

// ---------------- launch ----------------
extern "C" void kernel_launch(void* const* d_in, const int* in_sizes, int n_in,
                              void* d_out, int out_size) {
    const float* x     = (const float*)d_in[0];
    const int*   ei    = (const int*)d_in[1];
    const int*   batch = (const int*)d_in[2];
    const float* td_W1 = (const float*)d_in[4];
    const float* td_b1 = (const float*)d_in[5];
    const float* td_W2 = (const float*)d_in[6];
    const float* td_b2 = (const float*)d_in[7];
    const float* bu_W1 = (const float*)d_in[8];
    const float* bu_b1 = (const float*)d_in[9];
    const float* bu_W2 = (const float*)d_in[10];
    const float* bu_b2 = (const float*)d_in[11];
    const float* pw1   = (const float*)d_in[12];
    const float* pb1   = (const float*)d_in[13];
    const float* pw2   = (const float*)d_in[14];
    const float* pb2   = (const float*)d_in[15];
    float* out = (float*)d_out;

    float *buf1, *bufTd, *bufBu, *pool, *mlp, *dinv;
    int *deg, *off_td, *off_bu, *cur_td, *cur_bu, *part, *csr_td, *csr_bu;
    cudaGetSymbolAddress((void**)&buf1,   g_buf1);
    cudaGetSymbolAddress((void**)&bufTd,  g_bufTd);
    cudaGetSymbolAddress((void**)&bufBu,  g_bufBu);
    cudaGetSymbolAddress((void**)&pool,   g_pool);
    cudaGetSymbolAddress((void**)&mlp,    g_mlp);
    cudaGetSymbolAddress((void**)&dinv,   g_dinv);
    cudaGetSymbolAddress((void**)&deg,    g_deg);
    cudaGetSymbolAddress((void**)&off_td, g_off_td);
    cudaGetSymbolAddress((void**)&off_bu, g_off_bu);
    cudaGetSymbolAddress((void**)&cur_td, g_cur_td);
    cudaGetSymbolAddress((void**)&cur_bu, g_cur_bu);
    cudaGetSymbolAddress((void**)&part,   g_part);
    cudaGetSymbolAddress((void**)&csr_td, g_csr_td);
    cudaGetSymbolAddress((void**)&csr_bu, g_csr_bu);

    const int* src = ei;
    const int* dst = ei + EE;
    const float* dinv_td = dinv;
    const float* dinv_bu = dinv + NN;

    // --- graph structure ---
    zero_i<<<(2 * NN + 255) / 256, 256>>>(deg, 2 * NN);
    deg_kernel<<<(EE + 255) / 256, 256>>>(src, dst, deg, deg + NN, EE);
    dinv_kernel<<<(2 * NN + 255) / 256, 256>>>(deg, dinv, 2 * NN);
    scan_bsum<<<dim3(NBLK, 2), 256>>>(deg, part);
    scan_part<<<1, 64>>>(part, off_td, off_bu);
    scan_write<<<dim3(NBLK, 2), 256>>>(deg, part, off_td, off_bu, cur_td, cur_bu);
    scatter_kernel<<<(EE + 255) / 256, 256>>>(src, dst, cur_td, cur_bu, csr_td, csr_bu, EE);

    zero_f4<<<(NG * 64 + 255) / 256, 256>>>(pool, NG * 64);

    const int gx = (NN + 127) / 128;   // 391
    const int aggBlocks = (NN * 32 + 255) / 256;

    // conv1 GEMMs (prescaled by dinv): buf1[:, :128]=td, [:,128:]=bu
    gemm_tf32<<<dim3(gx, 1), 256>>>(x, td_W1, nullptr, dinv_td, buf1,       NN, 256, 128, 256, 0);
    gemm_tf32<<<dim3(gx, 1), 256>>>(x, bu_W1, nullptr, dinv_bu, buf1 + 128, NN, 256, 128, 256, 0);

    // conv1 aggregation + bias + relu
    agg_csr<<<aggBlocks, 256>>>(buf1, 256, 0,   csr_td, off_td, dinv_td, td_b1,
                                bufTd, 128, 0, 1, nullptr, nullptr, 0);
    agg_csr<<<aggBlocks, 256>>>(buf1, 256, 128, csr_bu, off_bu, dinv_bu, bu_b1,
                                bufBu, 128, 0, 1, nullptr, nullptr, 0);

    // conv2 GEMMs (prescaled)
    gemm_tf32<<<dim3(gx, 1), 256>>>(bufTd, td_W2, nullptr, dinv_td, buf1,       NN, 128, 128, 256, 0);
    gemm_tf32<<<dim3(gx, 1), 256>>>(bufBu, bu_W2, nullptr, dinv_bu, buf1 + 128, NN, 128, 128, 256, 0);

    // conv2 aggregation + bias, pooled into concat buffer [bu | td]
    agg_csr<<<aggBlocks, 256>>>(buf1, 256, 0,   csr_td, off_td, dinv_td, td_b2,
                                nullptr, 0, 0, 0, batch, pool, 128);
    agg_csr<<<aggBlocks, 256>>>(buf1, 256, 128, csr_bu, off_bu, dinv_bu, bu_b2,
                                nullptr, 0, 0, 0, batch, pool, 0);

    // MLP head
    gemm_tf32<<<dim3(4, 2), 256>>>(pool, pw1, pb1, nullptr, mlp, NG, 256, 256, 256, 1);
    gemm_tf32<<<dim3(4, 1), 256>>>(mlp,  pw2, pb2, nullptr, out, NG, 256, 128, 128, 0);
}

// round 5
// speedup vs baseline: 1.1889x; 1.1889x over previous
#include <cuda_runtime.h>
#include <cstdint>

#define NN 50000
#define EE 800000
#define NG 512
#define N4 (NN / 4)
#define NBLK 49

// ---------------- static device scratch ----------------
__device__ float g_buf1[NN * 256];       // GEMM outs [N,256] (td|bu halves)
__device__ float g_bufTd[NN * 128];
__device__ float g_bufBu[NN * 128];
__device__ float g_pool[NG * 256];       // pooled concat: bu @0, td @128
__device__ float g_mlp[NG * 256];
__device__ int   g_deg[2 * NN];
__device__ float g_dinv[2 * NN];
__device__ int   g_off_td[NN + 1];
__device__ int   g_off_bu[NN + 1];
__device__ int   g_cur_td[NN];
__device__ int   g_cur_bu[NN];
__device__ int   g_part[2 * NBLK];
__device__ int   g_csr_td[EE];
__device__ int   g_csr_bu[EE];
__device__ float g_W1cat[256 * 256];     // [td_W1 | bu_W1]

// ---------------- utility kernels ----------------
__global__ void zero_f4(float* p, int n4) {
    int i = blockIdx.x * blockDim.x + threadIdx.x;
    if (i < n4) ((float4*)p)[i] = make_float4(0.f, 0.f, 0.f, 0.f);
}
__global__ void zero_i(int* p, int n) {
    int i = blockIdx.x * blockDim.x + threadIdx.x;
    if (i < n) p[i] = 0;
}
__global__ void deg_kernel(const int* __restrict__ src, const int* __restrict__ dst,
                           int* deg_in, int* deg_out, int e) {
    int i = blockIdx.x * blockDim.x + threadIdx.x;
    if (i < e) {
        atomicAdd(&deg_in[dst[i]], 1);
        atomicAdd(&deg_out[src[i]], 1);
    }
}
__global__ void dinv_kernel(const int* __restrict__ deg, float* __restrict__ dinv, int n) {
    int i = blockIdx.x * blockDim.x + threadIdx.x;
    if (i < n) dinv[i] = rsqrtf((float)deg[i] + 1.0f);
}
__global__ void cat_w1(const float* __restrict__ td, const float* __restrict__ bu,
                       float* __restrict__ out) {
    int i = blockIdx.x * blockDim.x + threadIdx.x;
    if (i < 256 * 128) {
        int r = i >> 7, c = i & 127;
        out[r * 256 + c]       = td[i];
        out[r * 256 + 128 + c] = bu[i];
    }
}

// ---------------- 3-phase parallel scan (validated R4) ----------------
__global__ void scan_bsum(const int* __restrict__ deg, int* __restrict__ part) {
    int dir = blockIdx.y, b = blockIdx.x, tid = threadIdx.x;
    const int4* d4 = (const int4*)(deg + dir * NN);
    int i4 = b * 256 + tid;
    int s = 0;
    if (i4 < N4) { int4 v = d4[i4]; s = v.x + v.y + v.z + v.w; }
#pragma unroll
    for (int d = 16; d > 0; d >>= 1) s += __shfl_down_sync(0xffffffffu, s, d);
    __shared__ int wt[8];
    if ((tid & 31) == 0) wt[tid >> 5] = s;
    __syncthreads();
    if (tid < 8) {
        int v = wt[tid];
#pragma unroll
        for (int d = 4; d > 0; d >>= 1) v += __shfl_down_sync(0xffu, v, d);
        if (tid == 0) part[dir * NBLK + b] = v;
    }
}
__global__ void scan_part(int* __restrict__ part, int* __restrict__ off_td,
                          int* __restrict__ off_bu) {
    int w = threadIdx.x >> 5, lane = threadIdx.x & 31;
    if (w >= 2) return;
    int* p = part + w * NBLK;
    int v0 = (lane < NBLK) ? p[lane] : 0;
    int v1 = (lane + 32 < NBLK) ? p[lane + 32] : 0;
    int s0 = v0;
#pragma unroll
    for (int d = 1; d < 32; d <<= 1) {
        int t = __shfl_up_sync(0xffffffffu, s0, d);
        if (lane >= d) s0 += t;
    }
    int tot0 = __shfl_sync(0xffffffffu, s0, 31);
    int s1 = v1;
#pragma unroll
    for (int d = 1; d < 32; d <<= 1) {
        int t = __shfl_up_sync(0xffffffffu, s1, d);
        if (lane >= d) s1 += t;
    }
    s1 += tot0;
    if (lane < NBLK) p[lane] = s0 - v0;
    if (lane + 32 < NBLK) p[lane + 32] = s1 - v1;
    int total = __shfl_sync(0xffffffffu, s1, 31);
    if (lane == 0) (w == 0 ? off_td : off_bu)[NN] = total;
}
__global__ void scan_write(const int* __restrict__ deg, const int* __restrict__ part,
                           int* __restrict__ off_td, int* __restrict__ off_bu,
                           int* __restrict__ cur_td, int* __restrict__ cur_bu) {
    int dir = blockIdx.y, b = blockIdx.x, tid = threadIdx.x;
    int lane = tid & 31, w = tid >> 5;
    const int4* d4 = (const int4*)(deg + dir * NN);
    int i4 = b * 256 + tid;
    int4 v = make_int4(0, 0, 0, 0);
    if (i4 < N4) v = d4[i4];
    int ts = v.x + v.y + v.z + v.w;
    int incl = ts;
#pragma unroll
    for (int d = 1; d < 32; d <<= 1) {
        int t = __shfl_up_sync(0xffffffffu, incl, d);
        if (lane >= d) incl += t;
    }
    __shared__ int wt[8];
    if (lane == 31) wt[w] = incl;
    __syncthreads();
    if (w == 0 && lane < 8) {
        int x = wt[lane];
        int sx = x;
#pragma unroll
        for (int d = 1; d < 8; d <<= 1) {
            int t = __shfl_up_sync(0xffu, sx, d);
            if (lane >= d) sx += t;
        }
        wt[lane] = sx - x;
    }
    __syncthreads();
    int base = part[dir * NBLK + b] + wt[w] + (incl - ts);
    int* off = dir ? off_bu : off_td;
    int* cur = dir ? cur_bu : cur_td;
    if (i4 < N4) {
        int4 o;
        o.x = base;
        o.y = base + v.x;
        o.z = o.y + v.y;
        o.w = o.z + v.z;
        ((int4*)off)[i4] = o;
        ((int4*)cur)[i4] = o;
    }
}
__global__ void scatter_kernel(const int* __restrict__ src, const int* __restrict__ dst,
                               int* cur_td, int* cur_bu,
                               int* __restrict__ csr_td, int* __restrict__ csr_bu, int e) {
    int i = blockIdx.x * blockDim.x + threadIdx.x;
    if (i < e) {
        int s = src[i], d = dst[i];
        csr_td[atomicAdd(&cur_td[d], 1)] = s;
        csr_bu[atomicAdd(&cur_bu[s], 1)] = d;
    }
}

// ---------------- TF32 tensor-core GEMM (R3 design + rowscale epilogue) ----------------
__device__ __forceinline__ uint32_t f2tf(float x) {
    uint32_t r;
    asm("cvt.rna.tf32.f32 %0, %1;" : "=r"(r) : "f"(x));
    return r;
}

// C[M, n-window] = (A[M,K] @ B[K,ldb]) * rowscale (+bias, +relu).
// Block tile 128x128, kstep 32. rowscale selected per blockIdx.y (rs0/rs1).
__global__ __launch_bounds__(256, 2)
void gemm_tf32(const float* __restrict__ A, const float* __restrict__ B,
               const float* __restrict__ bias,
               const float* __restrict__ rs0, const float* __restrict__ rs1,
               float* __restrict__ C, int M, int K, int ldb, int ldc, int relu) {
    __shared__ uint32_t As[32][136];   // [k][m]
    __shared__ uint32_t Bs[32][136];   // [k][n]

    const int tid = threadIdx.x;
    const int lane = tid & 31;
    const int warp = tid >> 5;
    const int g = lane >> 2, tig = lane & 3;
    const int m0 = blockIdx.x * 128, n0 = blockIdx.y * 128;
    const int wm = (warp & 1) * 64, wn = (warp >> 1) * 32;
    const float* rowscale = (blockIdx.y == 0) ? rs0 : rs1;

    float acc[4][4][4];
#pragma unroll
    for (int i = 0; i < 4; i++)
#pragma unroll
        for (int j = 0; j < 4; j++)
#pragma unroll
            for (int c = 0; c < 4; c++) acc[i][j][c] = 0.f;

    for (int k0 = 0; k0 < K; k0 += 32) {
#pragma unroll
        for (int r = 0; r < 4; r++) {
            int m = lane + 32 * r;
            int gm = m0 + m;
            float4 v = make_float4(0.f, 0.f, 0.f, 0.f);
            if (gm < M) v = *(const float4*)(A + (size_t)gm * K + k0 + warp * 4);
            As[warp * 4 + 0][m] = f2tf(v.x);
            As[warp * 4 + 1][m] = f2tf(v.y);
            As[warp * 4 + 2][m] = f2tf(v.z);
            As[warp * 4 + 3][m] = f2tf(v.w);
        }
#pragma unroll
        for (int l = 0; l < 4; l++) {
            int idx = tid + l * 256;
            int k = idx >> 5, nf = idx & 31;
            float4 v = *(const float4*)(B + (size_t)(k0 + k) * ldb + n0 + nf * 4);
            uint32_t* p = &Bs[k][nf * 4];
            p[0] = f2tf(v.x); p[1] = f2tf(v.y); p[2] = f2tf(v.z); p[3] = f2tf(v.w);
        }
        __syncthreads();

#pragma unroll
        for (int kk = 0; kk < 32; kk += 8) {
            uint32_t af[4][4], bf[4][2];
#pragma unroll
            for (int i = 0; i < 4; i++) {
                int mb = wm + i * 16 + g;
                af[i][0] = As[kk + tig][mb];
                af[i][1] = As[kk + tig][mb + 8];
                af[i][2] = As[kk + tig + 4][mb];
                af[i][3] = As[kk + tig + 4][mb + 8];
            }
#pragma unroll
            for (int j = 0; j < 4; j++) {
                int nb = wn + j * 8 + g;
                bf[j][0] = Bs[kk + tig][nb];
                bf[j][1] = Bs[kk + tig + 4][nb];
            }
#pragma unroll
            for (int i = 0; i < 4; i++)
#pragma unroll
                for (int j = 0; j < 4; j++) {
                    asm volatile(
                        "mma.sync.aligned.m16n8k8.row.col.f32.tf32.tf32.f32 "
                        "{%0,%1,%2,%3}, {%4,%5,%6,%7}, {%8,%9}, {%0,%1,%2,%3};"
                        : "+f"(acc[i][j][0]), "+f"(acc[i][j][1]),
                          "+f"(acc[i][j][2]), "+f"(acc[i][j][3])
                        : "r"(af[i][0]), "r"(af[i][1]), "r"(af[i][2]), "r"(af[i][3]),
                          "r"(bf[j][0]), "r"(bf[j][1]));
                }
        }
        __syncthreads();
    }

#pragma unroll
    for (int i = 0; i < 4; i++) {
        int r0 = m0 + wm + i * 16 + g;
        int r1 = r0 + 8;
        float s0 = 1.f, s1 = 1.f;
        if (rowscale) {
            if (r0 < M) s0 = rowscale[r0];
            if (r1 < M) s1 = rowscale[r1];
        }
#pragma unroll
        for (int j = 0; j < 4; j++) {
            int cb = n0 + wn + j * 8 + 2 * tig;
            float b0 = 0.f, b1 = 0.f;
            if (bias) { b0 = bias[cb]; b1 = bias[cb + 1]; }
            float v0 = acc[i][j][0] * s0 + b0, v1 = acc[i][j][1] * s0 + b1;
            float v2 = acc[i][j][2] * s1 + b0, v3 = acc[i][j][3] * s1 + b1;
            if (relu) {
                v0 = fmaxf(v0, 0.f); v1 = fmaxf(v1, 0.f);
                v2 = fmaxf(v2, 0.f); v3 = fmaxf(v3, 0.f);
            }
            if (r0 < M) *(float2*)(C + (size_t)r0 * ldc + cb) = make_float2(v0, v1);
            if (r1 < M) *(float2*)(C + (size_t)r1 * ldc + cb) = make_float2(v2, v3);
        }
    }
}

// ---------------- CSR aggregation on prescaled h' = dinv*h (R3 loop shape) -------
// out[d] = act( dinv[d]*(Σ_s h'[s] + h'[d]) + b )
__global__ void agg_csr(const float* __restrict__ h, int hs, int ho,
                        const int* __restrict__ csr, const int* __restrict__ off,
                        const float* __restrict__ dinv, const float* __restrict__ bias,
                        float* __restrict__ out, int os, int oo, int relu,
                        const int* __restrict__ batch, float* __restrict__ pool, int po) {
    int node = (blockIdx.x * blockDim.x + threadIdx.x) >> 5;
    if (node >= NN) return;
    int lane = threadIdx.x & 31;

    int e0 = off[node], e1 = off[node + 1];
    float4 acc = make_float4(0.f, 0.f, 0.f, 0.f);
    for (int j = e0; j < e1; j++) {
        int s = csr[j];                 // warp-uniform -> broadcast
        float4 v = *(const float4*)(h + (size_t)s * hs + ho + lane * 4);
        acc.x += v.x; acc.y += v.y; acc.z += v.z; acc.w += v.w;
    }
    float di = dinv[node];
    float4 sv = *(const float4*)(h + (size_t)node * hs + ho + lane * 4);
    float4 bv = *(const float4*)(bias + lane * 4);
    float4 r;
    r.x = fmaf(di, acc.x + sv.x, bv.x);
    r.y = fmaf(di, acc.y + sv.y, bv.y);
    r.z = fmaf(di, acc.z + sv.z, bv.z);
    r.w = fmaf(di, acc.w + sv.w, bv.w);
    if (relu) {
        r.x = fmaxf(r.x, 0.f); r.y = fmaxf(r.y, 0.f);
        r.z = fmaxf(r.z, 0.f); r.w = fmaxf(r.w, 0.f);
    }
    if (pool) {
        int gi = batch[node];
        float* p = pool + (size_t)gi * 256 + po + lane * 4;
        atomicAdd(p + 0, r.x);
        atomicAdd(p + 1, r.y);
        atomicAdd(p + 2, r.z);
        atomicAdd(p + 3, r.w);
    } else {
        *(float4*)(out + (size_t)node * os + oo + lane * 4) = r;
    }
}

// ---------------- launch ----------------
extern "C" void kernel_launch(void* const* d_in, const int* in_sizes, int n_in,
                              void* d_out, int out_size) {
    const float* x     = (const float*)d_in[0];
    const int*   ei    = (const int*)d_in[1];
    const int*   batch = (const int*)d_in[2];
    const float* td_W1 = (const float*)d_in[4];
    const float* td_b1 = (const float*)d_in[5];
    const float* td_W2 = (const float*)d_in[6];
    const float* td_b2 = (const float*)d_in[7];
    const float* bu_W1 = (const float*)d_in[8];
    const float* bu_b1 = (const float*)d_in[9];
    const float* bu_W2 = (const float*)d_in[10];
    const float* bu_b2 = (const float*)d_in[11];
    const float* pw1   = (const float*)d_in[12];
    const float* pb1   = (const float*)d_in[13];
    const float* pw2   = (const float*)d_in[14];
    const float* pb2   = (const float*)d_in[15];
    float* out = (float*)d_out;

    float *buf1, *bufTd, *bufBu, *pool, *mlp, *dinv, *W1cat;
    int *deg, *off_td, *off_bu, *cur_td, *cur_bu, *part, *csr_td, *csr_bu;
    cudaGetSymbolAddress((void**)&buf1,   g_buf1);
    cudaGetSymbolAddress((void**)&bufTd,  g_bufTd);
    cudaGetSymbolAddress((void**)&bufBu,  g_bufBu);
    cudaGetSymbolAddress((void**)&pool,   g_pool);
    cudaGetSymbolAddress((void**)&mlp,    g_mlp);
    cudaGetSymbolAddress((void**)&dinv,   g_dinv);
    cudaGetSymbolAddress((void**)&W1cat,  g_W1cat);
    cudaGetSymbolAddress((void**)&deg,    g_deg);
    cudaGetSymbolAddress((void**)&off_td, g_off_td);
    cudaGetSymbolAddress((void**)&off_bu, g_off_bu);
    cudaGetSymbolAddress((void**)&cur_td, g_cur_td);
    cudaGetSymbolAddress((void**)&cur_bu, g_cur_bu);
    cudaGetSymbolAddress((void**)&part,   g_part);
    cudaGetSymbolAddress((void**)&csr_td, g_csr_td);
    cudaGetSymbolAddress((void**)&csr_bu, g_csr_bu);

    const int* src = ei;
    const int* dst = ei + EE;
    const float* dinv_td = dinv;
    const float* dinv_bu = dinv + NN;

    // --- graph structure ---
    zero_i<<<(2 * NN + 255) / 256, 256>>>(deg, 2 * NN);
    deg_kernel<<<(EE + 255) / 256, 256>>>(src, dst, deg, deg + NN, EE);
    dinv_kernel<<<(2 * NN + 255) / 256, 256>>>(deg, dinv, 2 * NN);
    scan_bsum<<<dim3(NBLK, 2), 256>>>(deg, part);
    scan_part<<<1, 64>>>(part, off_td, off_bu);
    scan_write<<<dim3(NBLK, 2), 256>>>(deg, part, off_td, off_bu, cur_td, cur_bu);
    scatter_kernel<<<(EE + 255) / 256, 256>>>(src, dst, cur_td, cur_bu, csr_td, csr_bu, EE);

    zero_f4<<<(NG * 64 + 255) / 256, 256>>>(pool, NG * 64);
    cat_w1<<<(256 * 128 + 255) / 256, 256>>>(td_W1, bu_W1, W1cat);

    const int gx = (NN + 127) / 128;   // 391
    const int aggBlocks = (NN * 32 + 255) / 256;

    // conv1 GEMM fused: buf1 = (x @ [td_W1|bu_W1]) * dinv (per-half rowscale)
    gemm_tf32<<<dim3(gx, 2), 256>>>(x, W1cat, nullptr, dinv_td, dinv_bu,
                                    buf1, NN, 256, 256, 256, 0);

    // conv1 aggregation + bias + relu
    agg_csr<<<aggBlocks, 256>>>(buf1, 256, 0,   csr_td, off_td, dinv_td, td_b1,
                                bufTd, 128, 0, 1, nullptr, nullptr, 0);
    agg_csr<<<aggBlocks, 256>>>(buf1, 256, 128, csr_bu, off_bu, dinv_bu, bu_b1,
                                bufBu, 128, 0, 1, nullptr, nullptr, 0);

    // conv2 GEMMs (prescaled)
    gemm_tf32<<<dim3(gx, 1), 256>>>(bufTd, td_W2, nullptr, dinv_td, nullptr,
                                    buf1,       NN, 128, 128, 256, 0);
    gemm_tf32<<<dim3(gx, 1), 256>>>(bufBu, bu_W2, nullptr, dinv_bu, nullptr,
                                    buf1 + 128, NN, 128, 128, 256, 0);

    // conv2 aggregation + bias, pooled into concat buffer [bu | td]
    agg_csr<<<aggBlocks, 256>>>(buf1, 256, 0,   csr_td, off_td, dinv_td, td_b2,
                                nullptr, 0, 0, 0, batch, pool, 128);
    agg_csr<<<aggBlocks, 256>>>(buf1, 256, 128, csr_bu, off_bu, dinv_bu, bu_b2,
                                nullptr, 0, 0, 0, batch, pool, 0);

    // MLP head
    gemm_tf32<<<dim3(4, 2), 256>>>(pool, pw1, pb1, nullptr, nullptr,
                                   mlp, NG, 256, 256, 256, 1);
    gemm_tf32<<<dim3(4, 1), 256>>>(mlp,  pw2, pb2, nullptr, nullptr,
                                   out, NG, 256, 128, 128, 0);
}

// round 6
// speedup vs baseline: 1.5422x; 1.2972x over previous
#include <cuda_runtime.h>
#include <cstdint>

#define NN 50000
#define EE 800000
#define NG 512
#define N4 (NN / 4)
#define NBLK 49

// ---------------- static device scratch ----------------
__device__ float g_buf1[NN * 256];       // GEMM outs [N,256] (td|bu halves)
__device__ float g_bufTd[NN * 128];
__device__ float g_bufBu[NN * 128];
__device__ float g_pool[NG * 256];       // pooled concat: bu @0, td @128
__device__ float g_mlp[NG * 256];
__device__ int   g_deg[2 * NN];
__device__ float g_dinv[2 * NN];
__device__ int   g_off_td[NN + 1];
__device__ int   g_off_bu[NN + 1];
__device__ int   g_cur_td[NN];
__device__ int   g_cur_bu[NN];
__device__ int   g_part[2 * NBLK];
__device__ int   g_csr_td[EE];
__device__ int   g_csr_bu[EE];
__device__ float g_W1cat[256 * 256];     // [td_W1 | bu_W1]

// ---------------- utility kernels ----------------
__global__ void zero_f4(float* p, int n4) {
    int i = blockIdx.x * blockDim.x + threadIdx.x;
    if (i < n4) ((float4*)p)[i] = make_float4(0.f, 0.f, 0.f, 0.f);
}
__global__ void zero_i(int* p, int n) {
    int i = blockIdx.x * blockDim.x + threadIdx.x;
    if (i < n) p[i] = 0;
}
__global__ void deg_kernel(const int* __restrict__ src, const int* __restrict__ dst,
                           int* deg_in, int* deg_out, int e) {
    int i = blockIdx.x * blockDim.x + threadIdx.x;
    if (i < e) {
        atomicAdd(&deg_in[dst[i]], 1);
        atomicAdd(&deg_out[src[i]], 1);
    }
}
__global__ void dinv_kernel(const int* __restrict__ deg, float* __restrict__ dinv, int n) {
    int i = blockIdx.x * blockDim.x + threadIdx.x;
    if (i < n) dinv[i] = rsqrtf((float)deg[i] + 1.0f);
}
__global__ void cat_w1(const float* __restrict__ td, const float* __restrict__ bu,
                       float* __restrict__ out) {
    int i = blockIdx.x * blockDim.x + threadIdx.x;
    if (i < 256 * 128) {
        int r = i >> 7, c = i & 127;
        out[r * 256 + c]       = td[i];
        out[r * 256 + 128 + c] = bu[i];
    }
}

// ---------------- 3-phase parallel scan (validated) ----------------
__global__ void scan_bsum(const int* __restrict__ deg, int* __restrict__ part) {
    int dir = blockIdx.y, b = blockIdx.x, tid = threadIdx.x;
    const int4* d4 = (const int4*)(deg + dir * NN);
    int i4 = b * 256 + tid;
    int s = 0;
    if (i4 < N4) { int4 v = d4[i4]; s = v.x + v.y + v.z + v.w; }
#pragma unroll
    for (int d = 16; d > 0; d >>= 1) s += __shfl_down_sync(0xffffffffu, s, d);
    __shared__ int wt[8];
    if ((tid & 31) == 0) wt[tid >> 5] = s;
    __syncthreads();
    if (tid < 8) {
        int v = wt[tid];
#pragma unroll
        for (int d = 4; d > 0; d >>= 1) v += __shfl_down_sync(0xffu, v, d);
        if (tid == 0) part[dir * NBLK + b] = v;
    }
}
__global__ void scan_part(int* __restrict__ part, int* __restrict__ off_td,
                          int* __restrict__ off_bu) {
    int w = threadIdx.x >> 5, lane = threadIdx.x & 31;
    if (w >= 2) return;
    int* p = part + w * NBLK;
    int v0 = (lane < NBLK) ? p[lane] : 0;
    int v1 = (lane + 32 < NBLK) ? p[lane + 32] : 0;
    int s0 = v0;
#pragma unroll
    for (int d = 1; d < 32; d <<= 1) {
        int t = __shfl_up_sync(0xffffffffu, s0, d);
        if (lane >= d) s0 += t;
    }
    int tot0 = __shfl_sync(0xffffffffu, s0, 31);
    int s1 = v1;
#pragma unroll
    for (int d = 1; d < 32; d <<= 1) {
        int t = __shfl_up_sync(0xffffffffu, s1, d);
        if (lane >= d) s1 += t;
    }
    s1 += tot0;
    if (lane < NBLK) p[lane] = s0 - v0;
    if (lane + 32 < NBLK) p[lane + 32] = s1 - v1;
    int total = __shfl_sync(0xffffffffu, s1, 31);
    if (lane == 0) (w == 0 ? off_td : off_bu)[NN] = total;
}
__global__ void scan_write(const int* __restrict__ deg, const int* __restrict__ part,
                           int* __restrict__ off_td, int* __restrict__ off_bu,
                           int* __restrict__ cur_td, int* __restrict__ cur_bu) {
    int dir = blockIdx.y, b = blockIdx.x, tid = threadIdx.x;
    int lane = tid & 31, w = tid >> 5;
    const int4* d4 = (const int4*)(deg + dir * NN);
    int i4 = b * 256 + tid;
    int4 v = make_int4(0, 0, 0, 0);
    if (i4 < N4) v = d4[i4];
    int ts = v.x + v.y + v.z + v.w;
    int incl = ts;
#pragma unroll
    for (int d = 1; d < 32; d <<= 1) {
        int t = __shfl_up_sync(0xffffffffu, incl, d);
        if (lane >= d) incl += t;
    }
    __shared__ int wt[8];
    if (lane == 31) wt[w] = incl;
    __syncthreads();
    if (w == 0 && lane < 8) {
        int x = wt[lane];
        int sx = x;
#pragma unroll
        for (int d = 1; d < 8; d <<= 1) {
            int t = __shfl_up_sync(0xffu, sx, d);
            if (lane >= d) sx += t;
        }
        wt[lane] = sx - x;
    }
    __syncthreads();
    int base = part[dir * NBLK + b] + wt[w] + (incl - ts);
    int* off = dir ? off_bu : off_td;
    int* cur = dir ? cur_bu : cur_td;
    if (i4 < N4) {
        int4 o;
        o.x = base;
        o.y = base + v.x;
        o.z = o.y + v.y;
        o.w = o.z + v.z;
        ((int4*)off)[i4] = o;
        ((int4*)cur)[i4] = o;
    }
}
__global__ void scatter_kernel(const int* __restrict__ src, const int* __restrict__ dst,
                               int* cur_td, int* cur_bu,
                               int* __restrict__ csr_td, int* __restrict__ csr_bu, int e) {
    int i = blockIdx.x * blockDim.x + threadIdx.x;
    if (i < e) {
        int s = src[i], d = dst[i];
        csr_td[atomicAdd(&cur_td[d], 1)] = s;
        csr_bu[atomicAdd(&cur_bu[s], 1)] = d;
    }
}

__device__ __forceinline__ uint32_t f2tf(float x) {
    uint32_t r;
    asm("cvt.rna.tf32.f32 %0, %1;" : "=r"(r) : "f"(x));
    return r;
}

// ---------------- pipelined TF32 GEMM (cp.async, BK=32, double-buffered) -----------
// Per-blockIdx.y pointer sets. C[y][M, 128-window] = (A[y] @ B[y]) * rs[y].
// smem words: As 2*128*36 = 9216, Bs 2*32*136 = 8704. Total 17920 w = 71680 B.
#define AS_W 4608
#define BS_W 4352
__global__ __launch_bounds__(256, 2)
void gemm_pipe(const float* __restrict__ A0, const float* __restrict__ A1,
               const float* __restrict__ B0, const float* __restrict__ B1,
               const float* __restrict__ rs0, const float* __restrict__ rs1,
               float* __restrict__ C0, float* __restrict__ C1,
               int M, int K, int ldb, int ldc) {
    extern __shared__ uint32_t sm[];
    const float* A = blockIdx.y ? A1 : A0;
    const float* B = blockIdx.y ? B1 : B0;
    const float* rowscale = blockIdx.y ? rs1 : rs0;
    float* C = blockIdx.y ? C1 : C0;

    const int tid = threadIdx.x;
    const int lane = tid & 31;
    const int warp = tid >> 5;
    const int g = lane >> 2, tig = lane & 3;
    const int m0 = blockIdx.x * 128;
    const int wm = (warp & 1) * 64, wn = (warp >> 1) * 32;

    const uint32_t sA = (uint32_t)__cvta_generic_to_shared(sm);
    const uint32_t sB = sA + 9216u * 4u;

    float acc[4][4][4];
#pragma unroll
    for (int i = 0; i < 4; i++)
#pragma unroll
        for (int j = 0; j < 4; j++)
#pragma unroll
            for (int c = 0; c < 4; c++) acc[i][j][c] = 0.f;

    const int T = K >> 5;

#define ISSUE(t)                                                                 \
    {                                                                            \
        const int k0 = (t) * 32;                                                 \
        const uint32_t ab = sA + (uint32_t)(((t) & 1) * AS_W * 4);               \
        const uint32_t bb = sB + (uint32_t)(((t) & 1) * BS_W * 4);               \
        _Pragma("unroll")                                                        \
        for (int l = 0; l < 4; l++) {                                            \
            int idx = tid + l * 256;                                             \
            int row = idx >> 3, kq = idx & 7;                                    \
            int gm = m0 + row;                                                   \
            const float* srcp = A + (size_t)(gm < M ? gm : 0) * K + k0 + kq * 4; \
            uint32_t dstp = ab + (uint32_t)((row * 36 + kq * 4) * 4);            \
            int sz = gm < M ? 16 : 0;                                            \
            asm volatile("cp.async.cg.shared.global [%0], [%1], 16, %2;"         \
                         :: "r"(dstp), "l"(srcp), "r"(sz));                      \
        }                                                                        \
        _Pragma("unroll")                                                        \
        for (int l = 0; l < 4; l++) {                                            \
            int idx = tid + l * 256;                                             \
            int row = idx >> 5, c4 = idx & 31;                                   \
            const float* srcp = B + (size_t)(k0 + row) * ldb + c4 * 4;           \
            uint32_t dstp = bb + (uint32_t)((row * 136 + c4 * 4) * 4);           \
            asm volatile("cp.async.cg.shared.global [%0], [%1], 16;"             \
                         :: "r"(dstp), "l"(srcp));                               \
        }                                                                        \
        asm volatile("cp.async.commit_group;");                                  \
    }

    ISSUE(0);
    for (int t = 0; t < T; t++) {
        if (t + 1 < T) {
            ISSUE(t + 1);
            asm volatile("cp.async.wait_group 1;");
        } else {
            asm volatile("cp.async.wait_group 0;");
        }
        __syncthreads();
        const float* Asf = (const float*)(sm + (t & 1) * AS_W);
        const float* Bsf = (const float*)(sm + 9216 + (t & 1) * BS_W);
#pragma unroll
        for (int kk = 0; kk < 32; kk += 8) {
            uint32_t af[4][4], bf[4][2];
#pragma unroll
            for (int i = 0; i < 4; i++) {
                int mb = wm + i * 16 + g;
                af[i][0] = f2tf(Asf[mb * 36 + kk + tig]);
                af[i][1] = f2tf(Asf[(mb + 8) * 36 + kk + tig]);
                af[i][2] = f2tf(Asf[mb * 36 + kk + tig + 4]);
                af[i][3] = f2tf(Asf[(mb + 8) * 36 + kk + tig + 4]);
            }
#pragma unroll
            for (int j = 0; j < 4; j++) {
                int nb = wn + j * 8 + g;
                bf[j][0] = f2tf(Bsf[(kk + tig) * 136 + nb]);
                bf[j][1] = f2tf(Bsf[(kk + tig + 4) * 136 + nb]);
            }
#pragma unroll
            for (int i = 0; i < 4; i++)
#pragma unroll
                for (int j = 0; j < 4; j++) {
                    asm volatile(
                        "mma.sync.aligned.m16n8k8.row.col.f32.tf32.tf32.f32 "
                        "{%0,%1,%2,%3}, {%4,%5,%6,%7}, {%8,%9}, {%0,%1,%2,%3};"
                        : "+f"(acc[i][j][0]), "+f"(acc[i][j][1]),
                          "+f"(acc[i][j][2]), "+f"(acc[i][j][3])
                        : "r"(af[i][0]), "r"(af[i][1]), "r"(af[i][2]), "r"(af[i][3]),
                          "r"(bf[j][0]), "r"(bf[j][1]));
                }
        }
        __syncthreads();
    }
#undef ISSUE

#pragma unroll
    for (int i = 0; i < 4; i++) {
        int r0 = m0 + wm + i * 16 + g;
        int r1 = r0 + 8;
        float s0 = (r0 < M) ? rowscale[r0] : 1.f;
        float s1 = (r1 < M) ? rowscale[r1] : 1.f;
#pragma unroll
        for (int j = 0; j < 4; j++) {
            int cb = wn + j * 8 + 2 * tig;
            if (r0 < M)
                *(float2*)(C + (size_t)r0 * ldc + cb) =
                    make_float2(acc[i][j][0] * s0, acc[i][j][1] * s0);
            if (r1 < M)
                *(float2*)(C + (size_t)r1 * ldc + cb) =
                    make_float2(acc[i][j][2] * s1, acc[i][j][3] * s1);
        }
    }
}

// ---------------- small TF32 GEMM for MLP head (R3/R5-proven) ----------------
__global__ __launch_bounds__(256, 2)
void gemm_tf32(const float* __restrict__ A, const float* __restrict__ B,
               const float* __restrict__ bias, float* __restrict__ C,
               int M, int K, int ldb, int ldc, int relu) {
    __shared__ uint32_t As[32][136];
    __shared__ uint32_t Bs[32][136];

    const int tid = threadIdx.x;
    const int lane = tid & 31;
    const int warp = tid >> 5;
    const int g = lane >> 2, tig = lane & 3;
    const int m0 = blockIdx.x * 128, n0 = blockIdx.y * 128;
    const int wm = (warp & 1) * 64, wn = (warp >> 1) * 32;

    float acc[4][4][4];
#pragma unroll
    for (int i = 0; i < 4; i++)
#pragma unroll
        for (int j = 0; j < 4; j++)
#pragma unroll
            for (int c = 0; c < 4; c++) acc[i][j][c] = 0.f;

    for (int k0 = 0; k0 < K; k0 += 32) {
#pragma unroll
        for (int r = 0; r < 4; r++) {
            int m = lane + 32 * r;
            int gm = m0 + m;
            float4 v = make_float4(0.f, 0.f, 0.f, 0.f);
            if (gm < M) v = *(const float4*)(A + (size_t)gm * K + k0 + warp * 4);
            As[warp * 4 + 0][m] = f2tf(v.x);
            As[warp * 4 + 1][m] = f2tf(v.y);
            As[warp * 4 + 2][m] = f2tf(v.z);
            As[warp * 4 + 3][m] = f2tf(v.w);
        }
#pragma unroll
        for (int l = 0; l < 4; l++) {
            int idx = tid + l * 256;
            int k = idx >> 5, nf = idx & 31;
            float4 v = *(const float4*)(B + (size_t)(k0 + k) * ldb + n0 + nf * 4);
            uint32_t* p = &Bs[k][nf * 4];
            p[0] = f2tf(v.x); p[1] = f2tf(v.y); p[2] = f2tf(v.z); p[3] = f2tf(v.w);
        }
        __syncthreads();
#pragma unroll
        for (int kk = 0; kk < 32; kk += 8) {
            uint32_t af[4][4], bf[4][2];
#pragma unroll
            for (int i = 0; i < 4; i++) {
                int mb = wm + i * 16 + g;
                af[i][0] = As[kk + tig][mb];
                af[i][1] = As[kk + tig][mb + 8];
                af[i][2] = As[kk + tig + 4][mb];
                af[i][3] = As[kk + tig + 4][mb + 8];
            }
#pragma unroll
            for (int j = 0; j < 4; j++) {
                int nb = wn + j * 8 + g;
                bf[j][0] = Bs[kk + tig][nb];
                bf[j][1] = Bs[kk + tig + 4][nb];
            }
#pragma unroll
            for (int i = 0; i < 4; i++)
#pragma unroll
                for (int j = 0; j < 4; j++) {
                    asm volatile(
                        "mma.sync.aligned.m16n8k8.row.col.f32.tf32.tf32.f32 "
                        "{%0,%1,%2,%3}, {%4,%5,%6,%7}, {%8,%9}, {%0,%1,%2,%3};"
                        : "+f"(acc[i][j][0]), "+f"(acc[i][j][1]),
                          "+f"(acc[i][j][2]), "+f"(acc[i][j][3])
                        : "r"(af[i][0]), "r"(af[i][1]), "r"(af[i][2]), "r"(af[i][3]),
                          "r"(bf[j][0]), "r"(bf[j][1]));
                }
        }
        __syncthreads();
    }

#pragma unroll
    for (int i = 0; i < 4; i++) {
        int r0 = m0 + wm + i * 16 + g;
        int r1 = r0 + 8;
#pragma unroll
        for (int j = 0; j < 4; j++) {
            int cb = n0 + wn + j * 8 + 2 * tig;
            float b0 = 0.f, b1 = 0.f;
            if (bias) { b0 = bias[cb]; b1 = bias[cb + 1]; }
            float v0 = acc[i][j][0] + b0, v1 = acc[i][j][1] + b1;
            float v2 = acc[i][j][2] + b0, v3 = acc[i][j][3] + b1;
            if (relu) {
                v0 = fmaxf(v0, 0.f); v1 = fmaxf(v1, 0.f);
                v2 = fmaxf(v2, 0.f); v3 = fmaxf(v3, 0.f);
            }
            if (r0 < M) *(float2*)(C + (size_t)r0 * ldc + cb) = make_float2(v0, v1);
            if (r1 < M) *(float2*)(C + (size_t)r1 * ldc + cb) = make_float2(v2, v3);
        }
    }
}

// ---------------- dual CSR aggregation (td: y=0, bu: y=1) -------------------------
// h' prescaled by dinv. out = act( dinv[d]*(Σ h'[s] + h'[d]) + b )
__global__ void agg_dual(const float* __restrict__ h,
                         const int* __restrict__ csr0, const int* __restrict__ csr1,
                         const int* __restrict__ off0, const int* __restrict__ off1,
                         const float* __restrict__ dv0, const float* __restrict__ dv1,
                         const float* __restrict__ b0, const float* __restrict__ b1,
                         float* __restrict__ out0, float* __restrict__ out1, int relu,
                         const int* __restrict__ batch, float* __restrict__ pool) {
    const int y = blockIdx.y;
    const int* csr = y ? csr1 : csr0;
    const int* off = y ? off1 : off0;
    const float* dinv = y ? dv1 : dv0;
    const float* bias = y ? b1 : b0;
    float* out = y ? out1 : out0;
    const int ho = y * 128;

    int node = (blockIdx.x * blockDim.x + threadIdx.x) >> 5;
    if (node >= NN) return;
    int lane = threadIdx.x & 31;

    int e0 = off[node], e1 = off[node + 1];
    float4 acc = make_float4(0.f, 0.f, 0.f, 0.f);
    for (int j = e0; j < e1; j++) {
        int s = csr[j];                 // warp-uniform -> broadcast
        float4 v = *(const float4*)(h + (size_t)s * 256 + ho + lane * 4);
        acc.x += v.x; acc.y += v.y; acc.z += v.z; acc.w += v.w;
    }
    float di = dinv[node];
    float4 sv = *(const float4*)(h + (size_t)node * 256 + ho + lane * 4);
    float4 bv = *(const float4*)(bias + lane * 4);
    float4 r;
    r.x = fmaf(di, acc.x + sv.x, bv.x);
    r.y = fmaf(di, acc.y + sv.y, bv.y);
    r.z = fmaf(di, acc.z + sv.z, bv.z);
    r.w = fmaf(di, acc.w + sv.w, bv.w);
    if (relu) {
        r.x = fmaxf(r.x, 0.f); r.y = fmaxf(r.y, 0.f);
        r.z = fmaxf(r.z, 0.f); r.w = fmaxf(r.w, 0.f);
    }
    if (pool) {
        int gi = batch[node];
        int po = y ? 0 : 128;           // td -> cols [128,256), bu -> [0,128)
        float* p = pool + (size_t)gi * 256 + po + lane * 4;
        atomicAdd(p + 0, r.x);
        atomicAdd(p + 1, r.y);
        atomicAdd(p + 2, r.z);
        atomicAdd(p + 3, r.w);
    } else {
        *(float4*)(out + (size_t)node * 128 + lane * 4) = r;
    }
}

// ---------------- launch ----------------
extern "C" void kernel_launch(void* const* d_in, const int* in_sizes, int n_in,
                              void* d_out, int out_size) {
    const float* x     = (const float*)d_in[0];
    const int*   ei    = (const int*)d_in[1];
    const int*   batch = (const int*)d_in[2];
    const float* td_W1 = (const float*)d_in[4];
    const float* td_b1 = (const float*)d_in[5];
    const float* td_W2 = (const float*)d_in[6];
    const float* td_b2 = (const float*)d_in[7];
    const float* bu_W1 = (const float*)d_in[8];
    const float* bu_b1 = (const float*)d_in[9];
    const float* bu_W2 = (const float*)d_in[10];
    const float* bu_b2 = (const float*)d_in[11];
    const float* pw1   = (const float*)d_in[12];
    const float* pb1   = (const float*)d_in[13];
    const float* pw2   = (const float*)d_in[14];
    const float* pb2   = (const float*)d_in[15];
    float* out = (float*)d_out;

    float *buf1, *bufTd, *bufBu, *pool, *mlp, *dinv, *W1cat;
    int *deg, *off_td, *off_bu, *cur_td, *cur_bu, *part, *csr_td, *csr_bu;
    cudaGetSymbolAddress((void**)&buf1,   g_buf1);
    cudaGetSymbolAddress((void**)&bufTd,  g_bufTd);
    cudaGetSymbolAddress((void**)&bufBu,  g_bufBu);
    cudaGetSymbolAddress((void**)&pool,   g_pool);
    cudaGetSymbolAddress((void**)&mlp,    g_mlp);
    cudaGetSymbolAddress((void**)&dinv,   g_dinv);
    cudaGetSymbolAddress((void**)&W1cat,  g_W1cat);
    cudaGetSymbolAddress((void**)&deg,    g_deg);
    cudaGetSymbolAddress((void**)&off_td, g_off_td);
    cudaGetSymbolAddress((void**)&off_bu, g_off_bu);
    cudaGetSymbolAddress((void**)&cur_td, g_cur_td);
    cudaGetSymbolAddress((void**)&cur_bu, g_cur_bu);
    cudaGetSymbolAddress((void**)&part,   g_part);
    cudaGetSymbolAddress((void**)&csr_td, g_csr_td);
    cudaGetSymbolAddress((void**)&csr_bu, g_csr_bu);

    const int* src = ei;
    const int* dst = ei + EE;
    const float* dinv_td = dinv;
    const float* dinv_bu = dinv + NN;

    static const int SMEM_PIPE = (2 * AS_W + 2 * BS_W) * 4;   // 71680 B
    cudaFuncSetAttribute(gemm_pipe, cudaFuncAttributeMaxDynamicSharedMemorySize, SMEM_PIPE);

    // --- graph structure ---
    zero_i<<<(2 * NN + 255) / 256, 256>>>(deg, 2 * NN);
    deg_kernel<<<(EE + 255) / 256, 256>>>(src, dst, deg, deg + NN, EE);
    dinv_kernel<<<(2 * NN + 255) / 256, 256>>>(deg, dinv, 2 * NN);
    scan_bsum<<<dim3(NBLK, 2), 256>>>(deg, part);
    scan_part<<<1, 64>>>(part, off_td, off_bu);
    scan_write<<<dim3(NBLK, 2), 256>>>(deg, part, off_td, off_bu, cur_td, cur_bu);
    scatter_kernel<<<(EE + 255) / 256, 256>>>(src, dst, cur_td, cur_bu, csr_td, csr_bu, EE);

    zero_f4<<<(NG * 64 + 255) / 256, 256>>>(pool, NG * 64);
    cat_w1<<<(256 * 128 + 255) / 256, 256>>>(td_W1, bu_W1, W1cat);

    const int gx = (NN + 127) / 128;   // 391
    const int aggBlocks = (NN * 32 + 255) / 256;

    // conv1 GEMM (one launch, both branches): buf1 = (x @ [td_W1|bu_W1]) * dinv
    gemm_pipe<<<dim3(gx, 2), 256, SMEM_PIPE>>>(
        x, x, W1cat, W1cat + 128, dinv_td, dinv_bu, buf1, buf1 + 128,
        NN, 256, 256, 256);

    // conv1 aggregation + bias + relu (both branches)
    agg_dual<<<dim3(aggBlocks, 2), 256>>>(buf1, csr_td, csr_bu, off_td, off_bu,
                                          dinv_td, dinv_bu, td_b1, bu_b1,
                                          bufTd, bufBu, 1, nullptr, nullptr);

    // conv2 GEMMs (one launch, both branches, prescaled)
    gemm_pipe<<<dim3(gx, 2), 256, SMEM_PIPE>>>(
        bufTd, bufBu, td_W2, bu_W2, dinv_td, dinv_bu, buf1, buf1 + 128,
        NN, 128, 128, 256);

    // conv2 aggregation + bias, pooled into concat buffer [bu | td]
    agg_dual<<<dim3(aggBlocks, 2), 256>>>(buf1, csr_td, csr_bu, off_td, off_bu,
                                          dinv_td, dinv_bu, td_b2, bu_b2,
                                          nullptr, nullptr, 0, batch, pool);

    // MLP head
    gemm_tf32<<<dim3(4, 2), 256>>>(pool, pw1, pb1, mlp, NG, 256, 256, 256, 1);
    gemm_tf32<<<dim3(4, 1), 256>>>(mlp,  pw2, pb2, out, NG, 256, 128, 128, 0);
}

// round 10
// speedup vs baseline: 1.8066x; 1.1714x over previous
#include <cuda_runtime.h>
#include <cuda_fp16.h>
#include <cstdint>

#define NN 50000
#define EE 800000
#define NG 512
#define N4 (NN / 4)
#define NBLK 49

// ---------------- static device scratch ----------------
__device__ __half g_xh[NN * 256];         // x in fp16
__device__ __half g_bufh[NN * 256];       // GEMM outs (prescaled), td cols 0-127, bu 128-255
__device__ __half g_h1td[NN * 128];       // h1 td (post conv1, fp16)
__device__ __half g_h1bu[NN * 128];
__device__ __half g_wt1[256 * 256];       // W1^T fp16 [n][k]: n<128 td, n>=128 bu ; k=256
__device__ __half g_wt2[256 * 128];       // W2^T fp16 [n][k]: n<128 td, else bu ; k=128
__device__ float  g_pool[NG * 256];       // pooled concat fp32: bu @0, td @128
__device__ float  g_mlp[NG * 256];
__device__ int    g_deg[2 * NN];
__device__ float  g_dinv[2 * NN];
__device__ int    g_off_td[NN + 1];
__device__ int    g_off_bu[NN + 1];
__device__ int    g_cur_td[NN];
__device__ int    g_cur_bu[NN];
__device__ int    g_part[2 * NBLK];
__device__ int    g_csr_td[EE];
__device__ int    g_csr_bu[EE];

// ---------------- utility kernels ----------------
__global__ void zero_f4(float* p, int n4) {
    int i = blockIdx.x * blockDim.x + threadIdx.x;
    if (i < n4) ((float4*)p)[i] = make_float4(0.f, 0.f, 0.f, 0.f);
}
__global__ void zero_i(int* p, int n) {
    int i = blockIdx.x * blockDim.x + threadIdx.x;
    if (i < n) p[i] = 0;
}
__global__ void deg_kernel(const int* __restrict__ src, const int* __restrict__ dst,
                           int* deg_in, int* deg_out, int e) {
    int i = blockIdx.x * blockDim.x + threadIdx.x;
    if (i < e) {
        atomicAdd(&deg_in[dst[i]], 1);
        atomicAdd(&deg_out[src[i]], 1);
    }
}
__global__ void dinv_kernel(const int* __restrict__ deg, float* __restrict__ dinv, int n) {
    int i = blockIdx.x * blockDim.x + threadIdx.x;
    if (i < n) dinv[i] = rsqrtf((float)deg[i] + 1.0f);
}

// convert x (fp32) -> fp16, 8 elems/thread
__global__ void cvt_x(const float* __restrict__ x, __half* __restrict__ xh, int n8) {
    int i = blockIdx.x * blockDim.x + threadIdx.x;
    if (i >= n8) return;
    const float4* x4 = (const float4*)x;
    float4 a = x4[2 * i], b = x4[2 * i + 1];
    __half2 h0 = __floats2half2_rn(a.x, a.y);
    __half2 h1 = __floats2half2_rn(a.z, a.w);
    __half2 h2 = __floats2half2_rn(b.x, b.y);
    __half2 h3 = __floats2half2_rn(b.z, b.w);
    uint4 o;
    o.x = *(uint32_t*)&h0; o.y = *(uint32_t*)&h1;
    o.z = *(uint32_t*)&h2; o.w = *(uint32_t*)&h3;
    ((uint4*)xh)[i] = o;
}

// build transposed fp16 weights: wt1[n][k] (k=256), wt2[n][k] (k=128)
__global__ void cvt_w(const float* __restrict__ tdW1, const float* __restrict__ buW1,
                      const float* __restrict__ tdW2, const float* __restrict__ buW2,
                      __half* __restrict__ wt1, __half* __restrict__ wt2) {
    int i = blockIdx.x * blockDim.x + threadIdx.x;
    if (i < 256 * 256) {
        int n = i >> 8, k = i & 255;
        float v = (n < 128) ? tdW1[k * 128 + n] : buW1[k * 128 + (n - 128)];
        wt1[n * 256 + k] = __float2half_rn(v);
    } else if (i < 256 * 256 + 256 * 128) {
        int j = i - 256 * 256;
        int n = j >> 7, k = j & 127;
        float v = (n < 128) ? tdW2[k * 128 + n] : buW2[k * 128 + (n - 128)];
        wt2[n * 128 + k] = __float2half_rn(v);
    }
}

// ---------------- 3-phase parallel scan (validated) ----------------
__global__ void scan_bsum(const int* __restrict__ deg, int* __restrict__ part) {
    int dir = blockIdx.y, b = blockIdx.x, tid = threadIdx.x;
    const int4* d4 = (const int4*)(deg + dir * NN);
    int i4 = b * 256 + tid;
    int s = 0;
    if (i4 < N4) { int4 v = d4[i4]; s = v.x + v.y + v.z + v.w; }
#pragma unroll
    for (int d = 16; d > 0; d >>= 1) s += __shfl_down_sync(0xffffffffu, s, d);
    __shared__ int wt[8];
    if ((tid & 31) == 0) wt[tid >> 5] = s;
    __syncthreads();
    if (tid < 8) {
        int v = wt[tid];
#pragma unroll
        for (int d = 4; d > 0; d >>= 1) v += __shfl_down_sync(0xffu, v, d);
        if (tid == 0) part[dir * NBLK + b] = v;
    }
}
__global__ void scan_part(int* __restrict__ part, int* __restrict__ off_td,
                          int* __restrict__ off_bu) {
    int w = threadIdx.x >> 5, lane = threadIdx.x & 31;
    if (w >= 2) return;
    int* p = part + w * NBLK;
    int v0 = (lane < NBLK) ? p[lane] : 0;
    int v1 = (lane + 32 < NBLK) ? p[lane + 32] : 0;
    int s0 = v0;
#pragma unroll
    for (int d = 1; d < 32; d <<= 1) {
        int t = __shfl_up_sync(0xffffffffu, s0, d);
        if (lane >= d) s0 += t;
    }
    int tot0 = __shfl_sync(0xffffffffu, s0, 31);
    int s1 = v1;
#pragma unroll
    for (int d = 1; d < 32; d <<= 1) {
        int t = __shfl_up_sync(0xffffffffu, s1, d);
        if (lane >= d) s1 += t;
    }
    s1 += tot0;
    if (lane < NBLK) p[lane] = s0 - v0;
    if (lane + 32 < NBLK) p[lane + 32] = s1 - v1;
    int total = __shfl_sync(0xffffffffu, s1, 31);
    if (lane == 0) (w == 0 ? off_td : off_bu)[NN] = total;
}
__global__ void scan_write(const int* __restrict__ deg, const int* __restrict__ part,
                           int* __restrict__ off_td, int* __restrict__ off_bu,
                           int* __restrict__ cur_td, int* __restrict__ cur_bu) {
    int dir = blockIdx.y, b = blockIdx.x, tid = threadIdx.x;
    int lane = tid & 31, w = tid >> 5;
    const int4* d4 = (const int4*)(deg + dir * NN);
    int i4 = b * 256 + tid;
    int4 v = make_int4(0, 0, 0, 0);
    if (i4 < N4) v = d4[i4];
    int ts = v.x + v.y + v.z + v.w;
    int incl = ts;
#pragma unroll
    for (int d = 1; d < 32; d <<= 1) {
        int t = __shfl_up_sync(0xffffffffu, incl, d);
        if (lane >= d) incl += t;
    }
    __shared__ int wt[8];
    if (lane == 31) wt[w] = incl;
    __syncthreads();
    if (w == 0 && lane < 8) {
        int x = wt[lane];
        int sx = x;
#pragma unroll
        for (int d = 1; d < 8; d <<= 1) {
            int t = __shfl_up_sync(0xffu, sx, d);
            if (lane >= d) sx += t;
        }
        wt[lane] = sx - x;
    }
    __syncthreads();
    int base = part[dir * NBLK + b] + wt[w] + (incl - ts);
    int* off = dir ? off_bu : off_td;
    int* cur = dir ? cur_bu : cur_td;
    if (i4 < N4) {
        int4 o;
        o.x = base;
        o.y = base + v.x;
        o.z = o.y + v.y;
        o.w = o.z + v.z;
        ((int4*)off)[i4] = o;
        ((int4*)cur)[i4] = o;
    }
}
__global__ void scatter_kernel(const int* __restrict__ src, const int* __restrict__ dst,
                               int* cur_td, int* cur_bu,
                               int* __restrict__ csr_td, int* __restrict__ csr_bu, int e) {
    int i = blockIdx.x * blockDim.x + threadIdx.x;
    if (i < e) {
        int s = src[i], d = dst[i];
        csr_td[atomicAdd(&cur_td[d], 1)] = s;
        csr_bu[atomicAdd(&cur_bu[s], 1)] = d;
    }
}

// ---------------- fp16 pipelined GEMM (cp.async, BK=32, double-buffered) ----------
// Tile 128m x 128n. A [M,lda] fp16 row-major; B [128][K] fp16 (n-major, transposed
// weights); C fp16 [M,ldc] = (A@B^T) * rowscale. Per-blockIdx.y pointer sets.
// smem: As/Bs rows padded to 40 halves (20-word stride -> conflict-free frags).
#define AH_HALVES (128 * 40)
__global__ __launch_bounds__(256, 2)
void gemm_h(const __half* __restrict__ A0, const __half* __restrict__ A1,
            const __half* __restrict__ B0, const __half* __restrict__ B1,
            const float* __restrict__ rs0, const float* __restrict__ rs1,
            __half* __restrict__ C0, __half* __restrict__ C1,
            int M, int K, int lda, int ldc) {
    __shared__ __align__(16) __half As[2][AH_HALVES];
    __shared__ __align__(16) __half Bs[2][AH_HALVES];

    const __half* A = blockIdx.y ? A1 : A0;
    const __half* B = blockIdx.y ? B1 : B0;
    const float* rowscale = blockIdx.y ? rs1 : rs0;
    __half* C = blockIdx.y ? C1 : C0;

    const int tid = threadIdx.x;
    const int lane = tid & 31;
    const int warp = tid >> 5;
    const int g = lane >> 2, tig = lane & 3;
    const int m0 = blockIdx.x * 128;
    const int wm = (warp & 1) * 64, wn = (warp >> 1) * 32;

    const uint32_t sA = (uint32_t)__cvta_generic_to_shared(&As[0][0]);
    const uint32_t sB = (uint32_t)__cvta_generic_to_shared(&Bs[0][0]);

    float acc[4][4][4];
#pragma unroll
    for (int i = 0; i < 4; i++)
#pragma unroll
        for (int j = 0; j < 4; j++)
#pragma unroll
            for (int c = 0; c < 4; c++) acc[i][j][c] = 0.f;

    const int T = K >> 5;

#define ISSUEH(t)                                                                   \
    {                                                                               \
        const int k0 = (t) * 32;                                                    \
        const uint32_t ab = sA + (uint32_t)(((t) & 1) * AH_HALVES * 2);             \
        const uint32_t bb = sB + (uint32_t)(((t) & 1) * AH_HALVES * 2);             \
        _Pragma("unroll")                                                           \
        for (int l = 0; l < 2; l++) {                                               \
            int idx = tid + l * 256;                                                \
            int row = idx >> 2, ck = idx & 3;                                       \
            int gm = m0 + row;                                                      \
            const __half* srcp = A + (size_t)(gm < M ? gm : 0) * lda + k0 + ck * 8; \
            uint32_t dstp = ab + (uint32_t)(row * 80 + ck * 16);                    \
            int sz = gm < M ? 16 : 0;                                               \
            asm volatile("cp.async.cg.shared.global [%0], [%1], 16, %2;"            \
                         :: "r"(dstp), "l"(srcp), "r"(sz));                         \
        }                                                                           \
        _Pragma("unroll")                                                           \
        for (int l = 0; l < 2; l++) {                                               \
            int idx = tid + l * 256;                                                \
            int nr = idx >> 2, ck = idx & 3;                                        \
            const __half* srcp = B + (size_t)nr * K + k0 + ck * 8;                  \
            uint32_t dstp = bb + (uint32_t)(nr * 80 + ck * 16);                     \
            asm volatile("cp.async.cg.shared.global [%0], [%1], 16;"                \
                         :: "r"(dstp), "l"(srcp));                                  \
        }                                                                           \
        asm volatile("cp.async.commit_group;");                                     \
    }

    ISSUEH(0);
    for (int t = 0; t < T; t++) {
        if (t + 1 < T) {
            ISSUEH(t + 1);
            asm volatile("cp.async.wait_group 1;");
        } else {
            asm volatile("cp.async.wait_group 0;");
        }
        __syncthreads();
        const uint32_t* Aw = (const uint32_t*)&As[t & 1][0];
        const uint32_t* Bw = (const uint32_t*)&Bs[t & 1][0];
#pragma unroll
        for (int kk = 0; kk < 32; kk += 16) {
            const int kw = kk >> 1;   // word offset of this k16 chunk
            uint32_t af[4][4], bf[4][2];
#pragma unroll
            for (int i = 0; i < 4; i++) {
                int mb = wm + i * 16 + g;
                af[i][0] = Aw[mb * 20 + kw + tig];
                af[i][1] = Aw[(mb + 8) * 20 + kw + tig];
                af[i][2] = Aw[mb * 20 + kw + 4 + tig];
                af[i][3] = Aw[(mb + 8) * 20 + kw + 4 + tig];
            }
#pragma unroll
            for (int j = 0; j < 4; j++) {
                int nb = wn + j * 8 + g;
                bf[j][0] = Bw[nb * 20 + kw + tig];
                bf[j][1] = Bw[nb * 20 + kw + 4 + tig];
            }
#pragma unroll
            for (int i = 0; i < 4; i++)
#pragma unroll
                for (int j = 0; j < 4; j++) {
                    asm volatile(
                        "mma.sync.aligned.m16n8k16.row.col.f32.f16.f16.f32 "
                        "{%0,%1,%2,%3}, {%4,%5,%6,%7}, {%8,%9}, {%0,%1,%2,%3};"
                        : "+f"(acc[i][j][0]), "+f"(acc[i][j][1]),
                          "+f"(acc[i][j][2]), "+f"(acc[i][j][3])
                        : "r"(af[i][0]), "r"(af[i][1]), "r"(af[i][2]), "r"(af[i][3]),
                          "r"(bf[j][0]), "r"(bf[j][1]));
                }
        }
        __syncthreads();
    }
#undef ISSUEH

#pragma unroll
    for (int i = 0; i < 4; i++) {
        int r0 = m0 + wm + i * 16 + g;
        int r1 = r0 + 8;
        float s0 = (r0 < M) ? rowscale[r0] : 1.f;
        float s1 = (r1 < M) ? rowscale[r1] : 1.f;
#pragma unroll
        for (int j = 0; j < 4; j++) {
            int cb = wn + j * 8 + 2 * tig;
            if (r0 < M) {
                __half2 p = __floats2half2_rn(acc[i][j][0] * s0, acc[i][j][1] * s0);
                *(__half2*)(C + (size_t)r0 * ldc + cb) = p;
            }
            if (r1 < M) {
                __half2 p = __floats2half2_rn(acc[i][j][2] * s1, acc[i][j][3] * s1);
                *(__half2*)(C + (size_t)r1 * ldc + cb) = p;
            }
        }
    }
}

// ---------------- small TF32 GEMM for MLP head (proven) ----------------
__device__ __forceinline__ uint32_t f2tf(float x) {
    uint32_t r;
    asm("cvt.rna.tf32.f32 %0, %1;" : "=r"(r) : "f"(x));
    return r;
}
__global__ __launch_bounds__(256, 2)
void gemm_tf32(const float* __restrict__ A, const float* __restrict__ B,
               const float* __restrict__ bias, float* __restrict__ C,
               int M, int K, int ldb, int ldc, int relu) {
    __shared__ uint32_t As[32][136];
    __shared__ uint32_t Bs[32][136];

    const int tid = threadIdx.x;
    const int lane = tid & 31;
    const int warp = tid >> 5;
    const int g = lane >> 2, tig = lane & 3;
    const int m0 = blockIdx.x * 128, n0 = blockIdx.y * 128;
    const int wm = (warp & 1) * 64, wn = (warp >> 1) * 32;

    float acc[4][4][4];
#pragma unroll
    for (int i = 0; i < 4; i++)
#pragma unroll
        for (int j = 0; j < 4; j++)
#pragma unroll
            for (int c = 0; c < 4; c++) acc[i][j][c] = 0.f;

    for (int k0 = 0; k0 < K; k0 += 32) {
#pragma unroll
        for (int r = 0; r < 4; r++) {
            int m = lane + 32 * r;
            int gm = m0 + m;
            float4 v = make_float4(0.f, 0.f, 0.f, 0.f);
            if (gm < M) v = *(const float4*)(A + (size_t)gm * K + k0 + warp * 4);
            As[warp * 4 + 0][m] = f2tf(v.x);
            As[warp * 4 + 1][m] = f2tf(v.y);
            As[warp * 4 + 2][m] = f2tf(v.z);
            As[warp * 4 + 3][m] = f2tf(v.w);
        }
#pragma unroll
        for (int l = 0; l < 4; l++) {
            int idx = tid + l * 256;
            int k = idx >> 5, nf = idx & 31;
            float4 v = *(const float4*)(B + (size_t)(k0 + k) * ldb + n0 + nf * 4);
            uint32_t* p = &Bs[k][nf * 4];
            p[0] = f2tf(v.x); p[1] = f2tf(v.y); p[2] = f2tf(v.z); p[3] = f2tf(v.w);
        }
        __syncthreads();
#pragma unroll
        for (int kk = 0; kk < 32; kk += 8) {
            uint32_t af[4][4], bf[4][2];
#pragma unroll
            for (int i = 0; i < 4; i++) {
                int mb = wm + i * 16 + g;
                af[i][0] = As[kk + tig][mb];
                af[i][1] = As[kk + tig][mb + 8];
                af[i][2] = As[kk + tig + 4][mb];
                af[i][3] = As[kk + tig + 4][mb + 8];
            }
#pragma unroll
            for (int j = 0; j < 4; j++) {
                int nb = wn + j * 8 + g;
                bf[j][0] = Bs[kk + tig][nb];
                bf[j][1] = Bs[kk + tig + 4][nb];
            }
#pragma unroll
            for (int i = 0; i < 4; i++)
#pragma unroll
                for (int j = 0; j < 4; j++) {
                    asm volatile(
                        "mma.sync.aligned.m16n8k8.row.col.f32.tf32.tf32.f32 "
                        "{%0,%1,%2,%3}, {%4,%5,%6,%7}, {%8,%9}, {%0,%1,%2,%3};"
                        : "+f"(acc[i][j][0]), "+f"(acc[i][j][1]),
                          "+f"(acc[i][j][2]), "+f"(acc[i][j][3])
                        : "r"(af[i][0]), "r"(af[i][1]), "r"(af[i][2]), "r"(af[i][3]),
                          "r"(bf[j][0]), "r"(bf[j][1]));
                }
        }
        __syncthreads();
    }

#pragma unroll
    for (int i = 0; i < 4; i++) {
        int r0 = m0 + wm + i * 16 + g;
        int r1 = r0 + 8;
#pragma unroll
        for (int j = 0; j < 4; j++) {
            int cb = n0 + wn + j * 8 + 2 * tig;
            float b0 = 0.f, b1 = 0.f;
            if (bias) { b0 = bias[cb]; b1 = bias[cb + 1]; }
            float v0 = acc[i][j][0] + b0, v1 = acc[i][j][1] + b1;
            float v2 = acc[i][j][2] + b0, v3 = acc[i][j][3] + b1;
            if (relu) {
                v0 = fmaxf(v0, 0.f); v1 = fmaxf(v1, 0.f);
                v2 = fmaxf(v2, 0.f); v3 = fmaxf(v3, 0.f);
            }
            if (r0 < M) *(float2*)(C + (size_t)r0 * ldc + cb) = make_float2(v0, v1);
            if (r1 < M) *(float2*)(C + (size_t)r1 * ldc + cb) = make_float2(v2, v3);
        }
    }
}

// ---------------- dual CSR aggregation, fp16 gather / fp32 accumulate -------------
// h prescaled by dinv. out = act( dinv[d]*(Σ h'[s] + h'[d]) + b )
__global__ void agg_dual_h(const __half* __restrict__ h,
                           const int* __restrict__ csr0, const int* __restrict__ csr1,
                           const int* __restrict__ off0, const int* __restrict__ off1,
                           const float* __restrict__ dv0, const float* __restrict__ dv1,
                           const float* __restrict__ b0, const float* __restrict__ b1,
                           __half* __restrict__ out0, __half* __restrict__ out1, int relu,
                           const int* __restrict__ batch, float* __restrict__ pool) {
    const int y = blockIdx.y;
    const int* csr = y ? csr1 : csr0;
    const int* off = y ? off1 : off0;
    const float* dinv = y ? dv1 : dv0;
    const float* bias = y ? b1 : b0;
    __half* out = y ? out1 : out0;
    const int ho = y * 128;

    int node = (blockIdx.x * blockDim.x + threadIdx.x) >> 5;
    if (node >= NN) return;
    int lane = threadIdx.x & 31;

    int e0 = off[node], e1 = off[node + 1];
    float4 acc = make_float4(0.f, 0.f, 0.f, 0.f);
    for (int j = e0; j < e1; j++) {
        int s = csr[j];                 // warp-uniform -> broadcast
        uint2 v = *(const uint2*)(h + (size_t)s * 256 + ho + lane * 4);
        float2 f0 = __half22float2(*(__half2*)&v.x);
        float2 f1 = __half22float2(*(__half2*)&v.y);
        acc.x += f0.x; acc.y += f0.y; acc.z += f1.x; acc.w += f1.y;
    }
    float di = dinv[node];
    uint2 sv2 = *(const uint2*)(h + (size_t)node * 256 + ho + lane * 4);
    float2 s0 = __half22float2(*(__half2*)&sv2.x);
    float2 s1 = __half22float2(*(__half2*)&sv2.y);
    float4 bv = *(const float4*)(bias + lane * 4);
    float4 r;
    r.x = fmaf(di, acc.x + s0.x, bv.x);
    r.y = fmaf(di, acc.y + s0.y, bv.y);
    r.z = fmaf(di, acc.z + s1.x, bv.z);
    r.w = fmaf(di, acc.w + s1.y, bv.w);
    if (relu) {
        r.x = fmaxf(r.x, 0.f); r.y = fmaxf(r.y, 0.f);
        r.z = fmaxf(r.z, 0.f); r.w = fmaxf(r.w, 0.f);
    }
    if (pool) {
        int gi = batch[node];
        int po = y ? 0 : 128;           // td -> cols [128,256), bu -> [0,128)
        float* p = pool + (size_t)gi * 256 + po + lane * 4;
        atomicAdd(p + 0, r.x);
        atomicAdd(p + 1, r.y);
        atomicAdd(p + 2, r.z);
        atomicAdd(p + 3, r.w);
    } else {
        __half2 o0 = __floats2half2_rn(r.x, r.y);
        __half2 o1 = __floats2half2_rn(r.z, r.w);
        uint2 o;
        o.x = *(uint32_t*)&o0; o.y = *(uint32_t*)&o1;
        *(uint2*)(out + (size_t)node * 128 + lane * 4) = o;
    }
}

// ---------------- launch ----------------
extern "C" void kernel_launch(void* const* d_in, const int* in_sizes, int n_in,
                              void* d_out, int out_size) {
    const float* x     = (const float*)d_in[0];
    const int*   ei    = (const int*)d_in[1];
    const int*   batch = (const int*)d_in[2];
    const float* td_W1 = (const float*)d_in[4];
    const float* td_b1 = (const float*)d_in[5];
    const float* td_W2 = (const float*)d_in[6];
    const float* td_b2 = (const float*)d_in[7];
    const float* bu_W1 = (const float*)d_in[8];
    const float* bu_b1 = (const float*)d_in[9];
    const float* bu_W2 = (const float*)d_in[10];
    const float* bu_b2 = (const float*)d_in[11];
    const float* pw1   = (const float*)d_in[12];
    const float* pb1   = (const float*)d_in[13];
    const float* pw2   = (const float*)d_in[14];
    const float* pb2   = (const float*)d_in[15];
    float* out = (float*)d_out;

    __half *xh, *bufh, *h1td, *h1bu, *wt1, *wt2;
    float *pool, *mlp, *dinv;
    int *deg, *off_td, *off_bu, *cur_td, *cur_bu, *part, *csr_td, *csr_bu;
    cudaGetSymbolAddress((void**)&xh,     g_xh);
    cudaGetSymbolAddress((void**)&bufh,   g_bufh);
    cudaGetSymbolAddress((void**)&h1td,   g_h1td);
    cudaGetSymbolAddress((void**)&h1bu,   g_h1bu);
    cudaGetSymbolAddress((void**)&wt1,    g_wt1);
    cudaGetSymbolAddress((void**)&wt2,    g_wt2);
    cudaGetSymbolAddress((void**)&pool,   g_pool);
    cudaGetSymbolAddress((void**)&mlp,    g_mlp);
    cudaGetSymbolAddress((void**)&dinv,   g_dinv);
    cudaGetSymbolAddress((void**)&deg,    g_deg);
    cudaGetSymbolAddress((void**)&off_td, g_off_td);
    cudaGetSymbolAddress((void**)&off_bu, g_off_bu);
    cudaGetSymbolAddress((void**)&cur_td, g_cur_td);
    cudaGetSymbolAddress((void**)&cur_bu, g_cur_bu);
    cudaGetSymbolAddress((void**)&part,   g_part);
    cudaGetSymbolAddress((void**)&csr_td, g_csr_td);
    cudaGetSymbolAddress((void**)&csr_bu, g_csr_bu);

    const int* src = ei;
    const int* dst = ei + EE;
    const float* dinv_td = dinv;
    const float* dinv_bu = dinv + NN;

    // --- graph structure ---
    zero_i<<<(2 * NN + 255) / 256, 256>>>(deg, 2 * NN);
    deg_kernel<<<(EE + 255) / 256, 256>>>(src, dst, deg, deg + NN, EE);
    dinv_kernel<<<(2 * NN + 255) / 256, 256>>>(deg, dinv, 2 * NN);
    scan_bsum<<<dim3(NBLK, 2), 256>>>(deg, part);
    scan_part<<<1, 64>>>(part, off_td, off_bu);
    scan_write<<<dim3(NBLK, 2), 256>>>(deg, part, off_td, off_bu, cur_td, cur_bu);
    scatter_kernel<<<(EE + 255) / 256, 256>>>(src, dst, cur_td, cur_bu, csr_td, csr_bu, EE);

    // --- converts + pool zero ---
    cvt_x<<<(NN * 32 + 255) / 256, 256>>>(x, xh, NN * 32);
    cvt_w<<<(256 * 256 + 256 * 128 + 255) / 256, 256>>>(td_W1, bu_W1, td_W2, bu_W2, wt1, wt2);
    zero_f4<<<(NG * 64 + 255) / 256, 256>>>(pool, NG * 64);

    const int gx = (NN + 127) / 128;   // 391
    const int aggBlocks = (NN * 32 + 255) / 256;

    // conv1 GEMM (both branches): bufh = (xh @ W1^T) * dinv
    gemm_h<<<dim3(gx, 2), 256>>>(xh, xh, wt1, wt1 + 128 * 256, dinv_td, dinv_bu,
                                 bufh, bufh + 128, NN, 256, 256, 256);

    // conv1 aggregation + bias + relu -> h1 (fp16)
    agg_dual_h<<<dim3(aggBlocks, 2), 256>>>(bufh, csr_td, csr_bu, off_td, off_bu,
                                            dinv_td, dinv_bu, td_b1, bu_b1,
                                            h1td, h1bu, 1, nullptr, nullptr);

    // conv2 GEMMs (both branches, prescaled)
    gemm_h<<<dim3(gx, 2), 256>>>(h1td, h1bu, wt2, wt2 + 128 * 128, dinv_td, dinv_bu,
                                 bufh, bufh + 128, NN, 128, 128, 256);

    // conv2 aggregation + bias, pooled into concat buffer [bu | td] (fp32)
    agg_dual_h<<<dim3(aggBlocks, 2), 256>>>(bufh, csr_td, csr_bu, off_td, off_bu,
                                            dinv_td, dinv_bu, td_b2, bu_b2,
                                            nullptr, nullptr, 0, batch, pool);

    // MLP head (fp32 tf32 path)
    gemm_tf32<<<dim3(4, 2), 256>>>(pool, pw1, pb1, mlp, NG, 256, 256, 256, 1);
    gemm_tf32<<<dim3(4, 1), 256>>>(mlp,  pw2, pb2, out, NG, 256, 128, 128, 0);
}